// round 1
// baseline (speedup 1.0000x reference)
#include <cuda_runtime.h>

#define TB   32
#define NTH  256

// smem floats: yR 2048, xR 2048, hA 8192, hB 8192, sS 2048, sT 2048,
//              bias1 256, bias2 256, b3 64, sc 64, mv 64, ld 32
#define SMEM_FLOATS (2048+2048+8192+8192+2048+2048+256+256+64+64+64+32)
#define SMEM_BYTES  (SMEM_FLOATS*4)

// Transposed weight scratch: [net][layer][K][N] layouts
__device__ __align__(256) float g_W1t[2][8*64*256];   // [k=64][n=256]
__device__ __align__(256) float g_W2t[2][8*256*256];  // [k=256][n=256]
__device__ __align__(256) float g_W3t[2][8*256*64];   // [k=256][n=64]

// ---------------- weight transpose ----------------
__global__ void tr_all(const float* __restrict__ sW1, const float* __restrict__ sW2,
                       const float* __restrict__ sW3, const float* __restrict__ tW1,
                       const float* __restrict__ tW2, const float* __restrict__ tW3)
{
    int tid = blockIdx.x * blockDim.x + threadIdx.x;
    int nt  = gridDim.x * blockDim.x;
    // W1 [8][256][64] -> [8][64][256]; W3 [8][64][256] -> [8][256][64]
    for (int i = tid; i < 8*256*64; i += nt) {
        int l = i >> 14, rem = i & 16383;
        int r = rem >> 6, c = rem & 63;              // W1: r=n(256), c=k(64)
        g_W1t[0][(l<<14) + (c<<8) + r] = sW1[i];
        g_W1t[1][(l<<14) + (c<<8) + r] = tW1[i];
        int r3 = rem >> 8, c3 = rem & 255;           // W3: r3=n(64), c3=k(256)
        g_W3t[0][(l<<14) + (c3<<6) + r3] = sW3[i];
        g_W3t[1][(l<<14) + (c3<<6) + r3] = tW3[i];
    }
    // W2 [8][256][256] -> [8][256][256] transposed
    for (int i = tid; i < 8*256*256; i += nt) {
        int l = i >> 16, rem = i & 65535;
        int r = rem >> 8, c = rem & 255;
        float v0 = sW2[i], v1 = tW2[i];
        g_W2t[0][(l<<16) + (c<<8) + r] = v0;
        g_W2t[1][(l<<16) + (c<<8) + r] = v1;
    }
}

// ---------------- helpers ----------------
__device__ __forceinline__ float tanh_fast(float x) {
    float e = __expf(2.0f * x);
    return 1.0f - __fdividef(2.0f, e + 1.0f);
}
__device__ __forceinline__ unsigned long long dup2(float x) {
    unsigned long long r;
    asm("mov.b64 %0, {%1, %1};" : "=l"(r) : "f"(x));
    return r;
}
__device__ __forceinline__ void fma2(unsigned long long& d, unsigned long long a,
                                     unsigned long long b) {
    asm("fma.rn.f32x2 %0, %1, %2, %0;" : "+l"(d) : "l"(a), "l"(b));
}
__device__ __forceinline__ float2 unpack2(unsigned long long v) {
    float lo, hi;
    asm("mov.b64 {%0, %1}, %2;" : "=f"(lo), "=f"(hi) : "l"(v));
    return make_float2(lo, hi);
}

// ---------------- GEMM N=256 (G1 / G2) ----------------
// out[r][c] = tanh( sum_k in[r][k]*Wt[k][c] + bias[c] (+ in[r][c] if SKIP) )
template<int K, int INSTRIDE, bool SKIP>
__device__ __forceinline__ void gemmN256(const float* __restrict__ Wt,
                                         const float* __restrict__ in,
                                         float* __restrict__ out,
                                         const float* __restrict__ bias, int tid)
{
    const int cg = tid & 31, rg = tid >> 5;
    const int cA = cg << 2;            // cols cA..cA+3
    const int cB = 128 + (cg << 2);    // cols cB..cB+3
    const int r0 = rg << 2;

    unsigned long long acc[4][4];
#pragma unroll
    for (int r = 0; r < 4; r++)
#pragma unroll
        for (int p = 0; p < 4; p++) acc[r][p] = 0ull;

    const float* in0 = in + (r0 + 0) * INSTRIDE;
    const float* in1 = in + (r0 + 1) * INSTRIDE;
    const float* in2 = in + (r0 + 2) * INSTRIDE;
    const float* in3 = in + (r0 + 3) * INSTRIDE;

#pragma unroll 2
    for (int k0 = 0; k0 < K; k0 += 4) {
        float4 a0 = *reinterpret_cast<const float4*>(in0 + k0);
        float4 a1 = *reinterpret_cast<const float4*>(in1 + k0);
        float4 a2 = *reinterpret_cast<const float4*>(in2 + k0);
        float4 a3 = *reinterpret_cast<const float4*>(in3 + k0);
#define KSTEP(kk, e0, e1, e2, e3)                                                  \
        {                                                                          \
            const float* wrow = Wt + (k0 + kk) * 256;                              \
            ulonglong2 wA = *reinterpret_cast<const ulonglong2*>(wrow + cA);       \
            ulonglong2 wB = *reinterpret_cast<const ulonglong2*>(wrow + cB);       \
            unsigned long long d0 = dup2(e0), d1 = dup2(e1);                       \
            unsigned long long d2 = dup2(e2), d3 = dup2(e3);                       \
            fma2(acc[0][0], d0, wA.x); fma2(acc[0][1], d0, wA.y);                  \
            fma2(acc[0][2], d0, wB.x); fma2(acc[0][3], d0, wB.y);                  \
            fma2(acc[1][0], d1, wA.x); fma2(acc[1][1], d1, wA.y);                  \
            fma2(acc[1][2], d1, wB.x); fma2(acc[1][3], d1, wB.y);                  \
            fma2(acc[2][0], d2, wA.x); fma2(acc[2][1], d2, wA.y);                  \
            fma2(acc[2][2], d2, wB.x); fma2(acc[2][3], d2, wB.y);                  \
            fma2(acc[3][0], d3, wA.x); fma2(acc[3][1], d3, wA.y);                  \
            fma2(acc[3][2], d3, wB.x); fma2(acc[3][3], d3, wB.y);                  \
        }
        KSTEP(0, a0.x, a1.x, a2.x, a3.x)
        KSTEP(1, a0.y, a1.y, a2.y, a3.y)
        KSTEP(2, a0.z, a1.z, a2.z, a3.z)
        KSTEP(3, a0.w, a1.w, a2.w, a3.w)
#undef KSTEP
    }

    float4 bA = *reinterpret_cast<const float4*>(&bias[cA]);
    float4 bB = *reinterpret_cast<const float4*>(&bias[cB]);
#pragma unroll
    for (int r = 0; r < 4; r++) {
        float2 vA0 = unpack2(acc[r][0]), vA1 = unpack2(acc[r][1]);
        float2 vB0 = unpack2(acc[r][2]), vB1 = unpack2(acc[r][3]);
        float oA0 = vA0.x + bA.x, oA1 = vA0.y + bA.y;
        float oA2 = vA1.x + bA.z, oA3 = vA1.y + bA.w;
        float oB0 = vB0.x + bB.x, oB1 = vB0.y + bB.y;
        float oB2 = vB1.x + bB.z, oB3 = vB1.y + bB.w;
        if (SKIP) {
            const float* irow = in + (r0 + r) * INSTRIDE;
            float4 sA = *reinterpret_cast<const float4*>(&irow[cA]);
            float4 sB = *reinterpret_cast<const float4*>(&irow[cB]);
            oA0 += sA.x; oA1 += sA.y; oA2 += sA.z; oA3 += sA.w;
            oB0 += sB.x; oB1 += sB.y; oB2 += sB.z; oB3 += sB.w;
        }
        float* orow = out + (r0 + r) * 256;
        float4 wOA = make_float4(tanh_fast(oA0), tanh_fast(oA1),
                                 tanh_fast(oA2), tanh_fast(oA3));
        float4 wOB = make_float4(tanh_fast(oB0), tanh_fast(oB1),
                                 tanh_fast(oB2), tanh_fast(oB3));
        *reinterpret_cast<float4*>(&orow[cA]) = wOA;
        *reinterpret_cast<float4*>(&orow[cB]) = wOB;
    }
}

// ---------------- GEMM N=64 (G3, both nets) ----------------
// SNET:  out = (tanh(acc + b3[c]) + xm[r][c]) * sc[c]
// !SNET: out = acc + b3[c] + xm[r][c]
template<bool SNET>
__device__ __forceinline__ void gemm64f(const float* __restrict__ Wt,  // [256][64]
                                        const float* __restrict__ in,  // [TB][256]
                                        const float* __restrict__ xmr, // [TB][64]
                                        float* __restrict__ outr,      // [TB][64]
                                        const float* __restrict__ b3,
                                        const float* __restrict__ sc, int tid)
{
    const int cg = tid & 31, rg = tid >> 5;
    const int c0 = cg << 1, r0 = rg << 2;
    unsigned long long acc[4] = {0ull, 0ull, 0ull, 0ull};

    const float* in0 = in + (r0 + 0) * 256;
    const float* in1 = in + (r0 + 1) * 256;
    const float* in2 = in + (r0 + 2) * 256;
    const float* in3 = in + (r0 + 3) * 256;

#pragma unroll 2
    for (int k0 = 0; k0 < 256; k0 += 4) {
        float4 a0 = *reinterpret_cast<const float4*>(in0 + k0);
        float4 a1 = *reinterpret_cast<const float4*>(in1 + k0);
        float4 a2 = *reinterpret_cast<const float4*>(in2 + k0);
        float4 a3 = *reinterpret_cast<const float4*>(in3 + k0);
#define K64(kk, e0, e1, e2, e3)                                                     \
        {                                                                           \
            unsigned long long w =                                                  \
                *reinterpret_cast<const unsigned long long*>(Wt + (k0+kk)*64 + c0); \
            fma2(acc[0], dup2(e0), w); fma2(acc[1], dup2(e1), w);                   \
            fma2(acc[2], dup2(e2), w); fma2(acc[3], dup2(e3), w);                   \
        }
        K64(0, a0.x, a1.x, a2.x, a3.x)
        K64(1, a0.y, a1.y, a2.y, a3.y)
        K64(2, a0.z, a1.z, a2.z, a3.z)
        K64(3, a0.w, a1.w, a2.w, a3.w)
#undef K64
    }

    float2 b = *reinterpret_cast<const float2*>(&b3[c0]);
    float2 scv = make_float2(0.f, 0.f);
    if (SNET) scv = *reinterpret_cast<const float2*>(&sc[c0]);
#pragma unroll
    for (int r = 0; r < 4; r++) {
        float2 v  = unpack2(acc[r]);
        float2 xm = *reinterpret_cast<const float2*>(&xmr[(r0 + r) * 64 + c0]);
        float o0, o1;
        if (SNET) {
            o0 = (tanh_fast(v.x + b.x) + xm.x) * scv.x;
            o1 = (tanh_fast(v.y + b.y) + xm.y) * scv.y;
        } else {
            o0 = v.x + b.x + xm.x;
            o1 = v.y + b.y + xm.y;
        }
        *reinterpret_cast<float2*>(&outr[(r0 + r) * 64 + c0]) = make_float2(o0, o1);
    }
}

// ---------------- main flow kernel ----------------
__global__ void __launch_bounds__(NTH, 2)
flow_kernel(const float* __restrict__ x, const float* __restrict__ masks,
            const float* __restrict__ sb1, const float* __restrict__ sb2,
            const float* __restrict__ sb3, const float* __restrict__ scale,
            const float* __restrict__ tb1, const float* __restrict__ tb2,
            const float* __restrict__ tb3,
            float* __restrict__ out, int B, long long ld_off)
{
    extern __shared__ float sm[];
    float* yR    = sm;            // [32][64]
    float* xR    = yR + 2048;     // [32][64]
    float* hA    = xR + 2048;     // [32][256]
    float* hB    = hA + 8192;     // [32][256]
    float* sS    = hB + 8192;     // [32][64]
    float* sT    = sS + 2048;     // [32][64]
    float* bias1 = sT + 2048;     // [256]
    float* bias2 = bias1 + 256;   // [256]
    float* b3s   = bias2 + 256;   // [64]
    float* scs   = b3s + 64;      // [64]
    float* mv    = scs + 64;      // [64]
    float* ldac  = mv + 64;       // [32]

    const int tid = threadIdx.x;
    const int gb  = blockIdx.x * TB;

    // load y tile (coalesced, row-major matches global)
    for (int i = tid; i < TB * 64; i += NTH) yR[i] = x[(long long)gb * 64 + i];
    if (tid < TB) ldac[tid] = 0.f;
    __syncthreads();

    for (int layer = 0; layer < 8; layer++) {
        if (tid < 64) mv[tid] = masks[layer * 64 + tid];
        __syncthreads();
        for (int i = tid; i < TB * 64; i += NTH) xR[i] = yR[i] * mv[i & 63];

#pragma unroll 1
        for (int net = 0; net < 2; net++) {
            const float* W1 = &g_W1t[net][layer * (64 * 256)];
            const float* W2 = &g_W2t[net][layer * (256 * 256)];
            const float* W3 = &g_W3t[net][layer * (256 * 64)];
            const float* b1 = (net ? tb1 : sb1) + layer * 256;
            const float* b2 = (net ? tb2 : sb2) + layer * 256;
            const float* b3 = (net ? tb3 : sb3) + layer * 64;
            bias1[tid] = b1[tid];
            bias2[tid] = b2[tid];
            if (tid < 64) {
                b3s[tid] = b3[tid];
                if (net == 0) scs[tid] = scale[layer * 64 + tid];
            }
            __syncthreads();
            gemmN256<64, 64, false>(W1, xR, hA, bias1, tid);
            __syncthreads();
            gemmN256<256, 256, true>(W2, hA, hB, bias2, tid);
            __syncthreads();
            if (net == 0) gemm64f<true >(W3, hB, xR, sS, b3s, scs, tid);
            else          gemm64f<false>(W3, hB, xR, sT, b3s, scs, tid);
            __syncthreads();
        }

        // coupling update + logdet
        {
            const int r  = tid >> 3;       // 0..31
            const int db = tid & 7;        // 0..7
            const int d0 = db << 3;        // 8 consecutive d per thread
            float part = 0.f;
#pragma unroll
            for (int v = 0; v < 2; v++) {
                int d = d0 + v * 4;
                float4 yv = *reinterpret_cast<const float4*>(&yR[r * 64 + d]);
                float4 s4 = *reinterpret_cast<const float4*>(&sS[r * 64 + d]);
                float4 t4 = *reinterpret_cast<const float4*>(&sT[r * 64 + d]);
                float4 m4 = *reinterpret_cast<const float4*>(&mv[d]);
                float4 yn;
                {
                    float im = 1.f - m4.x;
                    yn.x = m4.x * yv.x + im * (yv.x * __expf(s4.x) + t4.x);
                    part += im * s4.x;
                }
                {
                    float im = 1.f - m4.y;
                    yn.y = m4.y * yv.y + im * (yv.y * __expf(s4.y) + t4.y);
                    part += im * s4.y;
                }
                {
                    float im = 1.f - m4.z;
                    yn.z = m4.z * yv.z + im * (yv.z * __expf(s4.z) + t4.z);
                    part += im * s4.z;
                }
                {
                    float im = 1.f - m4.w;
                    yn.w = m4.w * yv.w + im * (yv.w * __expf(s4.w) + t4.w);
                    part += im * s4.w;
                }
                *reinterpret_cast<float4*>(&yR[r * 64 + d]) = yn;
            }
            part += __shfl_down_sync(0xffffffffu, part, 4, 8);
            part += __shfl_down_sync(0xffffffffu, part, 2, 8);
            part += __shfl_down_sync(0xffffffffu, part, 1, 8);
            if (db == 0) ldac[r] += part;
        }
        __syncthreads();
    }

    // write y and logdet
    for (int i = tid; i < TB * 64; i += NTH) out[(long long)gb * 64 + i] = yR[i];
    if (tid < TB) out[ld_off + gb + tid] = ldac[tid];
}

// ---------------- launch ----------------
extern "C" void kernel_launch(void* const* d_in, const int* in_sizes, int n_in,
                              void* d_out, int out_size)
{
    const float* x     = (const float*)d_in[0];
    const float* masks = (const float*)d_in[1];
    const float* sW1   = (const float*)d_in[2];
    const float* sb1   = (const float*)d_in[3];
    const float* sW2   = (const float*)d_in[4];
    const float* sb2   = (const float*)d_in[5];
    const float* sW3   = (const float*)d_in[6];
    const float* sb3   = (const float*)d_in[7];
    const float* scale = (const float*)d_in[8];
    const float* tW1   = (const float*)d_in[9];
    const float* tb1   = (const float*)d_in[10];
    const float* tW2   = (const float*)d_in[11];
    const float* tb2   = (const float*)d_in[12];
    const float* tW3   = (const float*)d_in[13];
    const float* tb3   = (const float*)d_in[14];

    const int B = in_sizes[0] / 64;
    const long long ld_off = (long long)out_size - B;  // y first, logdet last

    cudaFuncSetAttribute(flow_kernel, cudaFuncAttributeMaxDynamicSharedMemorySize,
                         SMEM_BYTES);

    tr_all<<<256, 256>>>(sW1, sW2, sW3, tW1, tW2, tW3);
    flow_kernel<<<B / TB, NTH, SMEM_BYTES>>>(x, masks, sb1, sb2, sb3, scale,
                                             tb1, tb2, tb3, (float*)d_out, B,
                                             ld_off);
}

// round 2
// speedup vs baseline: 1.0012x; 1.0012x over previous
#include <cuda_runtime.h>

#define TB   32
#define NTH  256

// smem floats: yR 2048, xR 2048, hA 8192, hB 8192, sS 2048, sT 2048,
//              bias1 256, bias2 256, b3 64, sc 64, mv 64, ld 32
#define SMEM_FLOATS (2048+2048+8192+8192+2048+2048+256+256+64+64+64+32)
#define SMEM_BYTES  (SMEM_FLOATS*4)

// Transposed weight scratch: [net][layer][K][N] layouts
__device__ __align__(256) float g_W1t[2][8*64*256];   // [k=64][n=256]
__device__ __align__(256) float g_W2t[2][8*256*256];  // [k=256][n=256]
__device__ __align__(256) float g_W3t[2][8*256*64];   // [k=256][n=64]

// ---------------- weight transpose ----------------
__global__ void tr_all(const float* __restrict__ sW1, const float* __restrict__ sW2,
                       const float* __restrict__ sW3, const float* __restrict__ tW1,
                       const float* __restrict__ tW2, const float* __restrict__ tW3)
{
    int tid = blockIdx.x * blockDim.x + threadIdx.x;
    int nt  = gridDim.x * blockDim.x;
    // W1 [8][256][64] -> [8][64][256]; W3 [8][64][256] -> [8][256][64]
    for (int i = tid; i < 8*256*64; i += nt) {
        int l = i >> 14, rem = i & 16383;
        int r = rem >> 6, c = rem & 63;              // W1: r=n(256), c=k(64)
        g_W1t[0][(l<<14) + (c<<8) + r] = sW1[i];
        g_W1t[1][(l<<14) + (c<<8) + r] = tW1[i];
        int r3 = rem >> 8, c3 = rem & 255;           // W3: r3=n(64), c3=k(256)
        g_W3t[0][(l<<14) + (c3<<6) + r3] = sW3[i];
        g_W3t[1][(l<<14) + (c3<<6) + r3] = tW3[i];
    }
    // W2 [8][256][256] -> [8][256][256] transposed
    for (int i = tid; i < 8*256*256; i += nt) {
        int l = i >> 16, rem = i & 65535;
        int r = rem >> 8, c = rem & 255;
        float v0 = sW2[i], v1 = tW2[i];
        g_W2t[0][(l<<16) + (c<<8) + r] = v0;
        g_W2t[1][(l<<16) + (c<<8) + r] = v1;
    }
}

// ---------------- helpers ----------------
__device__ __forceinline__ float tanh_fast(float x) {
    float e = __expf(2.0f * x);
    return 1.0f - __fdividef(2.0f, e + 1.0f);
}
__device__ __forceinline__ unsigned long long dup2(float x) {
    unsigned long long r;
    asm("mov.b64 %0, {%1, %1};" : "=l"(r) : "f"(x));
    return r;
}
__device__ __forceinline__ void fma2(unsigned long long& d, unsigned long long a,
                                     unsigned long long b) {
    asm("fma.rn.f32x2 %0, %1, %2, %0;" : "+l"(d) : "l"(a), "l"(b));
}
__device__ __forceinline__ float2 unpack2(unsigned long long v) {
    float lo, hi;
    asm("mov.b64 {%0, %1}, %2;" : "=f"(lo), "=f"(hi) : "l"(v));
    return make_float2(lo, hi);
}

// ---------------- GEMM N=256 (G1 / G2) ----------------
// out[r][c] = tanh( sum_k in[r][k]*Wt[k][c] + bias[c] (+ in[r][c] if SKIP) )
template<int K, int INSTRIDE, bool SKIP>
__device__ __forceinline__ void gemmN256(const float* __restrict__ Wt,
                                         const float* __restrict__ in,
                                         float* __restrict__ out,
                                         const float* __restrict__ bias, int tid)
{
    const int cg = tid & 31, rg = tid >> 5;
    const int cA = cg << 2;            // cols cA..cA+3
    const int cB = 128 + (cg << 2);    // cols cB..cB+3
    const int r0 = rg << 2;

    unsigned long long acc[4][4];
#pragma unroll
    for (int r = 0; r < 4; r++)
#pragma unroll
        for (int p = 0; p < 4; p++) acc[r][p] = 0ull;

    const float* in0 = in + (r0 + 0) * INSTRIDE;
    const float* in1 = in + (r0 + 1) * INSTRIDE;
    const float* in2 = in + (r0 + 2) * INSTRIDE;
    const float* in3 = in + (r0 + 3) * INSTRIDE;

#pragma unroll 2
    for (int k0 = 0; k0 < K; k0 += 4) {
        float4 a0 = *reinterpret_cast<const float4*>(in0 + k0);
        float4 a1 = *reinterpret_cast<const float4*>(in1 + k0);
        float4 a2 = *reinterpret_cast<const float4*>(in2 + k0);
        float4 a3 = *reinterpret_cast<const float4*>(in3 + k0);
#define KSTEP(kk, e0, e1, e2, e3)                                                  \
        {                                                                          \
            const float* wrow = Wt + (k0 + kk) * 256;                              \
            ulonglong2 wA = *reinterpret_cast<const ulonglong2*>(wrow + cA);       \
            ulonglong2 wB = *reinterpret_cast<const ulonglong2*>(wrow + cB);       \
            unsigned long long d0 = dup2(e0), d1 = dup2(e1);                       \
            unsigned long long d2 = dup2(e2), d3 = dup2(e3);                       \
            fma2(acc[0][0], d0, wA.x); fma2(acc[0][1], d0, wA.y);                  \
            fma2(acc[0][2], d0, wB.x); fma2(acc[0][3], d0, wB.y);                  \
            fma2(acc[1][0], d1, wA.x); fma2(acc[1][1], d1, wA.y);                  \
            fma2(acc[1][2], d1, wB.x); fma2(acc[1][3], d1, wB.y);                  \
            fma2(acc[2][0], d2, wA.x); fma2(acc[2][1], d2, wA.y);                  \
            fma2(acc[2][2], d2, wB.x); fma2(acc[2][3], d2, wB.y);                  \
            fma2(acc[3][0], d3, wA.x); fma2(acc[3][1], d3, wA.y);                  \
            fma2(acc[3][2], d3, wB.x); fma2(acc[3][3], d3, wB.y);                  \
        }
        KSTEP(0, a0.x, a1.x, a2.x, a3.x)
        KSTEP(1, a0.y, a1.y, a2.y, a3.y)
        KSTEP(2, a0.z, a1.z, a2.z, a3.z)
        KSTEP(3, a0.w, a1.w, a2.w, a3.w)
#undef KSTEP
    }

    float4 bA = *reinterpret_cast<const float4*>(&bias[cA]);
    float4 bB = *reinterpret_cast<const float4*>(&bias[cB]);
#pragma unroll
    for (int r = 0; r < 4; r++) {
        float2 vA0 = unpack2(acc[r][0]), vA1 = unpack2(acc[r][1]);
        float2 vB0 = unpack2(acc[r][2]), vB1 = unpack2(acc[r][3]);
        float oA0 = vA0.x + bA.x, oA1 = vA0.y + bA.y;
        float oA2 = vA1.x + bA.z, oA3 = vA1.y + bA.w;
        float oB0 = vB0.x + bB.x, oB1 = vB0.y + bB.y;
        float oB2 = vB1.x + bB.z, oB3 = vB1.y + bB.w;
        if (SKIP) {
            const float* irow = in + (r0 + r) * INSTRIDE;
            float4 sA = *reinterpret_cast<const float4*>(&irow[cA]);
            float4 sB = *reinterpret_cast<const float4*>(&irow[cB]);
            oA0 += sA.x; oA1 += sA.y; oA2 += sA.z; oA3 += sA.w;
            oB0 += sB.x; oB1 += sB.y; oB2 += sB.z; oB3 += sB.w;
        }
        float* orow = out + (r0 + r) * 256;
        float4 wOA = make_float4(tanh_fast(oA0), tanh_fast(oA1),
                                 tanh_fast(oA2), tanh_fast(oA3));
        float4 wOB = make_float4(tanh_fast(oB0), tanh_fast(oB1),
                                 tanh_fast(oB2), tanh_fast(oB3));
        *reinterpret_cast<float4*>(&orow[cA]) = wOA;
        *reinterpret_cast<float4*>(&orow[cB]) = wOB;
    }
}

// ---------------- GEMM N=64 (G3, both nets) ----------------
// SNET:  out = (tanh(acc + b3[c]) + xm[r][c]) * sc[c]
// !SNET: out = acc + b3[c] + xm[r][c]
template<bool SNET>
__device__ __forceinline__ void gemm64f(const float* __restrict__ Wt,  // [256][64]
                                        const float* __restrict__ in,  // [TB][256]
                                        const float* __restrict__ xmr, // [TB][64]
                                        float* __restrict__ outr,      // [TB][64]
                                        const float* __restrict__ b3,
                                        const float* __restrict__ sc, int tid)
{
    const int cg = tid & 31, rg = tid >> 5;
    const int c0 = cg << 1, r0 = rg << 2;
    unsigned long long acc[4] = {0ull, 0ull, 0ull, 0ull};

    const float* in0 = in + (r0 + 0) * 256;
    const float* in1 = in + (r0 + 1) * 256;
    const float* in2 = in + (r0 + 2) * 256;
    const float* in3 = in + (r0 + 3) * 256;

#pragma unroll 2
    for (int k0 = 0; k0 < 256; k0 += 4) {
        float4 a0 = *reinterpret_cast<const float4*>(in0 + k0);
        float4 a1 = *reinterpret_cast<const float4*>(in1 + k0);
        float4 a2 = *reinterpret_cast<const float4*>(in2 + k0);
        float4 a3 = *reinterpret_cast<const float4*>(in3 + k0);
#define K64(kk, e0, e1, e2, e3)                                                     \
        {                                                                           \
            unsigned long long w =                                                  \
                *reinterpret_cast<const unsigned long long*>(Wt + (k0+kk)*64 + c0); \
            fma2(acc[0], dup2(e0), w); fma2(acc[1], dup2(e1), w);                   \
            fma2(acc[2], dup2(e2), w); fma2(acc[3], dup2(e3), w);                   \
        }
        K64(0, a0.x, a1.x, a2.x, a3.x)
        K64(1, a0.y, a1.y, a2.y, a3.y)
        K64(2, a0.z, a1.z, a2.z, a3.z)
        K64(3, a0.w, a1.w, a2.w, a3.w)
#undef K64
    }

    float2 b = *reinterpret_cast<const float2*>(&b3[c0]);
    float2 scv = make_float2(0.f, 0.f);
    if (SNET) scv = *reinterpret_cast<const float2*>(&sc[c0]);
#pragma unroll
    for (int r = 0; r < 4; r++) {
        float2 v  = unpack2(acc[r]);
        float2 xm = *reinterpret_cast<const float2*>(&xmr[(r0 + r) * 64 + c0]);
        float o0, o1;
        if (SNET) {
            o0 = (tanh_fast(v.x + b.x) + xm.x) * scv.x;
            o1 = (tanh_fast(v.y + b.y) + xm.y) * scv.y;
        } else {
            o0 = v.x + b.x + xm.x;
            o1 = v.y + b.y + xm.y;
        }
        *reinterpret_cast<float2*>(&outr[(r0 + r) * 64 + c0]) = make_float2(o0, o1);
    }
}

// ---------------- main flow kernel ----------------
__global__ void __launch_bounds__(NTH, 2)
flow_kernel(const float* __restrict__ x, const float* __restrict__ masks,
            const float* __restrict__ sb1, const float* __restrict__ sb2,
            const float* __restrict__ sb3, const float* __restrict__ scale,
            const float* __restrict__ tb1, const float* __restrict__ tb2,
            const float* __restrict__ tb3,
            float* __restrict__ out, int B, long long ld_off)
{
    extern __shared__ float sm[];
    float* yR    = sm;            // [32][64]
    float* xR    = yR + 2048;     // [32][64]
    float* hA    = xR + 2048;     // [32][256]
    float* hB    = hA + 8192;     // [32][256]
    float* sS    = hB + 8192;     // [32][64]
    float* sT    = sS + 2048;     // [32][64]
    float* bias1 = sT + 2048;     // [256]
    float* bias2 = bias1 + 256;   // [256]
    float* b3s   = bias2 + 256;   // [64]
    float* scs   = b3s + 64;      // [64]
    float* mv    = scs + 64;      // [64]
    float* ldac  = mv + 64;       // [32]

    const int tid = threadIdx.x;
    const int gb  = blockIdx.x * TB;

    // load y tile (coalesced, row-major matches global)
    for (int i = tid; i < TB * 64; i += NTH) yR[i] = x[(long long)gb * 64 + i];
    if (tid < TB) ldac[tid] = 0.f;
    __syncthreads();

    for (int layer = 0; layer < 8; layer++) {
        if (tid < 64) mv[tid] = masks[layer * 64 + tid];
        __syncthreads();
        for (int i = tid; i < TB * 64; i += NTH) xR[i] = yR[i] * mv[i & 63];

#pragma unroll 1
        for (int net = 0; net < 2; net++) {
            const float* W1 = &g_W1t[net][layer * (64 * 256)];
            const float* W2 = &g_W2t[net][layer * (256 * 256)];
            const float* W3 = &g_W3t[net][layer * (256 * 64)];
            const float* b1 = (net ? tb1 : sb1) + layer * 256;
            const float* b2 = (net ? tb2 : sb2) + layer * 256;
            const float* b3 = (net ? tb3 : sb3) + layer * 64;
            bias1[tid] = b1[tid];
            bias2[tid] = b2[tid];
            if (tid < 64) {
                b3s[tid] = b3[tid];
                if (net == 0) scs[tid] = scale[layer * 64 + tid];
            }
            __syncthreads();
            gemmN256<64, 64, false>(W1, xR, hA, bias1, tid);
            __syncthreads();
            gemmN256<256, 256, true>(W2, hA, hB, bias2, tid);
            __syncthreads();
            if (net == 0) gemm64f<true >(W3, hB, xR, sS, b3s, scs, tid);
            else          gemm64f<false>(W3, hB, xR, sT, b3s, scs, tid);
            __syncthreads();
        }

        // coupling update + logdet
        {
            const int r  = tid >> 3;       // 0..31
            const int db = tid & 7;        // 0..7
            const int d0 = db << 3;        // 8 consecutive d per thread
            float part = 0.f;
#pragma unroll
            for (int v = 0; v < 2; v++) {
                int d = d0 + v * 4;
                float4 yv = *reinterpret_cast<const float4*>(&yR[r * 64 + d]);
                float4 s4 = *reinterpret_cast<const float4*>(&sS[r * 64 + d]);
                float4 t4 = *reinterpret_cast<const float4*>(&sT[r * 64 + d]);
                float4 m4 = *reinterpret_cast<const float4*>(&mv[d]);
                float4 yn;
                {
                    float im = 1.f - m4.x;
                    yn.x = m4.x * yv.x + im * (yv.x * __expf(s4.x) + t4.x);
                    part += im * s4.x;
                }
                {
                    float im = 1.f - m4.y;
                    yn.y = m4.y * yv.y + im * (yv.y * __expf(s4.y) + t4.y);
                    part += im * s4.y;
                }
                {
                    float im = 1.f - m4.z;
                    yn.z = m4.z * yv.z + im * (yv.z * __expf(s4.z) + t4.z);
                    part += im * s4.z;
                }
                {
                    float im = 1.f - m4.w;
                    yn.w = m4.w * yv.w + im * (yv.w * __expf(s4.w) + t4.w);
                    part += im * s4.w;
                }
                *reinterpret_cast<float4*>(&yR[r * 64 + d]) = yn;
            }
            part += __shfl_down_sync(0xffffffffu, part, 4, 8);
            part += __shfl_down_sync(0xffffffffu, part, 2, 8);
            part += __shfl_down_sync(0xffffffffu, part, 1, 8);
            if (db == 0) ldac[r] += part;
        }
        __syncthreads();
    }

    // write y and logdet
    for (int i = tid; i < TB * 64; i += NTH) out[(long long)gb * 64 + i] = yR[i];
    if (tid < TB) out[ld_off + gb + tid] = ldac[tid];
}

// ---------------- launch ----------------
extern "C" void kernel_launch(void* const* d_in, const int* in_sizes, int n_in,
                              void* d_out, int out_size)
{
    const float* x     = (const float*)d_in[0];
    const float* masks = (const float*)d_in[1];
    const float* sW1   = (const float*)d_in[2];
    const float* sb1   = (const float*)d_in[3];
    const float* sW2   = (const float*)d_in[4];
    const float* sb2   = (const float*)d_in[5];
    const float* sW3   = (const float*)d_in[6];
    const float* sb3   = (const float*)d_in[7];
    const float* scale = (const float*)d_in[8];
    const float* tW1   = (const float*)d_in[9];
    const float* tb1   = (const float*)d_in[10];
    const float* tW2   = (const float*)d_in[11];
    const float* tb2   = (const float*)d_in[12];
    const float* tW3   = (const float*)d_in[13];
    const float* tb3   = (const float*)d_in[14];

    const int B = in_sizes[0] / 64;
    const long long ld_off = (long long)out_size - B;  // y first, logdet last

    cudaFuncSetAttribute(flow_kernel, cudaFuncAttributeMaxDynamicSharedMemorySize,
                         SMEM_BYTES);

    tr_all<<<256, 256>>>(sW1, sW2, sW3, tW1, tW2, tW3);
    flow_kernel<<<B / TB, NTH, SMEM_BYTES>>>(x, masks, sb1, sb2, sb3, scale,
                                             tb1, tb2, tb3, (float*)d_out, B,
                                             ld_off);
}